// round 11
// baseline (speedup 1.0000x reference)
#include <cuda_runtime.h>
#include <cuda_bf16.h>
#include <cstdint>

// Problem constants
#define N_NODES 100000
#define N_EDGES 1600000
#define IN_DIM  512
#define HID_DIM 128
#define OUT_DIM 64

// ---------------------------------------------------------------------------
// Scratch (static __device__ globals). NEVER passed as kernel arguments from
// host code (host-side symbol decay -> ATS-dereferenceable host shadow addr).
// All access happens from device code.
// ---------------------------------------------------------------------------
__device__ __align__(16) float g_support[(size_t)N_NODES * HID_DIM];
__device__ __align__(16) float g_h[(size_t)N_NODES * HID_DIM];
__device__ __align__(16) float g_hw[(size_t)N_NODES * OUT_DIM];
__device__ int   g_rowptr[N_NODES + 1];
__device__ int   g_cursor[N_NODES];
__device__ __align__(16) int   g_cols[N_EDGES];
__device__ __align__(16) float g_vals[N_EDGES];
__device__ int   g_bsums[64];
__device__ int   g_inrange[3];
__device__ const int*   g_erow_p;
__device__ const int*   g_ecol_p;
__device__ const float* g_evals_p;

// ---------------------------------------------------------------------------
// Input classification (proven in R7): vals = E-sized array whose sampled
// elements are NOT index-like.
// ---------------------------------------------------------------------------
#define CLS_SAMPLES (N_EDGES / 64)   // 25000

__global__ void zero_misc_kernel() {
    int i = blockIdx.x * blockDim.x + threadIdx.x;
    if (i <= N_NODES) g_rowptr[i] = 0;
    if (i < 3) g_inrange[i] = 0;
}

__global__ void classify_kernel(const int* __restrict__ a0,
                                const int* __restrict__ a1,
                                const int* __restrict__ a2) {
    __shared__ int s[3];
    if (threadIdx.x < 3) s[threadIdx.x] = 0;
    __syncthreads();
    int i = blockIdx.x * blockDim.x + threadIdx.x;
    if (i < CLS_SAMPLES) {
        int idx = i * 64;
        if ((unsigned)__ldg(a0 + idx) < (unsigned)N_NODES) atomicAdd(&s[0], 1);
        if ((unsigned)__ldg(a1 + idx) < (unsigned)N_NODES) atomicAdd(&s[1], 1);
        if ((unsigned)__ldg(a2 + idx) < (unsigned)N_NODES) atomicAdd(&s[2], 1);
    }
    __syncthreads();
    if (threadIdx.x < 3) atomicAdd(&g_inrange[threadIdx.x], s[threadIdx.x]);
}

__global__ void select_kernel(const int* a0, const int* a1, const int* a2) {
    int c0 = g_inrange[0], c1 = g_inrange[1], c2 = g_inrange[2];
    int vi = (c0 <= c1 && c0 <= c2) ? 0 : ((c1 <= c2) ? 1 : 2);
    const int* arr[3] = {a0, a1, a2};
    int o0 = (vi == 0) ? 1 : 0;
    int o1 = (vi == 2) ? 1 : 2;
    g_erow_p  = arr[o0];                  // metadata order: row before col
    g_ecol_p  = arr[o1];
    g_evals_p = (const float*)arr[vi];
}

// ---------------------------------------------------------------------------
// CSR build — 4 edges/thread, vector loads
// ---------------------------------------------------------------------------
__global__ void hist_kernel() {
    const int* __restrict__ erow = g_erow_p;
    int i = (blockIdx.x * blockDim.x + threadIdx.x) * 4;
    if (i < N_EDGES) {  // N_EDGES % 4 == 0
        int4 r = *reinterpret_cast<const int4*>(erow + i);
        if ((unsigned)r.x < (unsigned)N_NODES) atomicAdd(&g_rowptr[r.x + 1], 1);
        if ((unsigned)r.y < (unsigned)N_NODES) atomicAdd(&g_rowptr[r.y + 1], 1);
        if ((unsigned)r.z < (unsigned)N_NODES) atomicAdd(&g_rowptr[r.z + 1], 1);
        if ((unsigned)r.w < (unsigned)N_NODES) atomicAdd(&g_rowptr[r.w + 1], 1);
    }
}

// inclusive scan pass 1: 2048 elems per block (256 thr x 8)
__global__ void scan_partial_kernel() {
    const int TPB = 256, ITEMS = 8, PER = TPB * ITEMS;
    const int L = N_NODES + 1;
    __shared__ int s[TPB];
    int base = blockIdx.x * PER + threadIdx.x * ITEMS;
    int v[ITEMS];
    int running = 0;
#pragma unroll
    for (int i = 0; i < ITEMS; i++) {
        int x = (base + i < L) ? g_rowptr[base + i] : 0;
        running += x;
        v[i] = running;
    }
    s[threadIdx.x] = running;
    __syncthreads();
    for (int off = 1; off < TPB; off <<= 1) {
        int t = (threadIdx.x >= off) ? s[threadIdx.x - off] : 0;
        __syncthreads();
        s[threadIdx.x] += t;
        __syncthreads();
    }
    int excl = s[threadIdx.x] - running;
#pragma unroll
    for (int i = 0; i < ITEMS; i++)
        if (base + i < L) g_rowptr[base + i] = v[i] + excl;
    if (threadIdx.x == TPB - 1) g_bsums[blockIdx.x] = s[TPB - 1];
}

__global__ void scan_sums_kernel(int nb) {
    if (threadIdx.x == 0 && blockIdx.x == 0) {
        int acc = 0;
        for (int i = 0; i < nb; i++) {
            int t = g_bsums[i];
            g_bsums[i] = acc;
            acc += t;
        }
    }
}

__global__ void scan_add_kernel() {
    const int L = N_NODES + 1;
    int i = blockIdx.x * blockDim.x + threadIdx.x;
    if (i < L) {
        int v = g_rowptr[i] + g_bsums[i / 2048];
        g_rowptr[i] = v;
        if (i < N_NODES) g_cursor[i] = v;
    }
}

__global__ void scatter_kernel() {
    const int*   __restrict__ erow  = g_erow_p;
    const int*   __restrict__ ecol  = g_ecol_p;
    const float* __restrict__ evals = g_evals_p;
    int i = (blockIdx.x * blockDim.x + threadIdx.x) * 4;
    if (i < N_EDGES) {
        int4   r4 = *reinterpret_cast<const int4*>(erow + i);
        int4   c4 = *reinterpret_cast<const int4*>(ecol + i);
        float4 v4 = *reinterpret_cast<const float4*>(evals + i);
        int    rr[4] = {r4.x, r4.y, r4.z, r4.w};
        int    cc[4] = {c4.x, c4.y, c4.z, c4.w};
        float  vv[4] = {v4.x, v4.y, v4.z, v4.w};
#pragma unroll
        for (int j = 0; j < 4; j++) {
            unsigned r = (unsigned)rr[j];
            if (r >= (unsigned)N_NODES) continue;
            unsigned c = (unsigned)cc[j];
            if (c >= (unsigned)N_NODES) c = N_NODES - 1;
            int p = atomicAdd(&g_cursor[r], 1);
            g_cols[p] = (int)c;
            g_vals[p] = vv[j];
        }
    }
}

// ---------------------------------------------------------------------------
// Double-buffered tiled fp32 GEMM: C[M,N] = A[M,K] @ B[K,N]
//   BM=128, BK=16, 256 threads. TN=8 uses split-half N mapping so b-side
//   LDS.128 is conflict-free (16 consecutive float4s per half).
//   LAYER 1: A=feature(arg) -> g_support.  LAYER 2: A=g_h -> g_hw.
// ---------------------------------------------------------------------------
template <int LAYER, int BM, int BN, int BK, int TM, int TN, int K, int N>
__global__ __launch_bounds__(256, 2)
void gemm_kernel(const float* __restrict__ A_in, const float* __restrict__ B,
                 int M) {
    const float* __restrict__ A = (LAYER == 1) ? A_in : (const float*)g_h;
    float* __restrict__ C = (LAYER == 1) ? (float*)g_support : (float*)g_hw;

    constexpr int THREADS = 256;
    static_assert((BM / TM) * (BN / TN) == THREADS, "thread count mismatch");
    constexpr int ASTRIDE = BM + 4;
    constexpr int A_LD = BM * BK / (4 * THREADS);
    constexpr int B_LD = BK * BN / (4 * THREADS);

    __shared__ float As[2][BK][ASTRIDE];
    __shared__ float Bs[2][BK][BN];

    const int tid = threadIdx.x;
    constexpr int nGroups = BN / TN;
    const int n_idx = tid % nGroups;
    const int m_idx = tid / nGroups;
    const int row0 = blockIdx.x * BM;

    float4 pa[A_LD], pb[B_LD];

    auto ldA = [&](int k0) {
#pragma unroll
        for (int u = 0; u < A_LD; u++) {
            int i = tid + u * THREADS;
            int r = i / (BK / 4);
            int c4 = (i % (BK / 4)) * 4;
            int gr = row0 + r;
            pa[u] = (gr < M)
                ? *reinterpret_cast<const float4*>(A + (size_t)gr * K + k0 + c4)
                : make_float4(0.f, 0.f, 0.f, 0.f);
        }
    };
    auto ldB = [&](int k0) {
#pragma unroll
        for (int u = 0; u < B_LD; u++) {
            int i = tid + u * THREADS;
            int r = i / (BN / 4);
            int c4 = (i % (BN / 4)) * 4;
            pb[u] = *reinterpret_cast<const float4*>(B + (size_t)(k0 + r) * N + c4);
        }
    };
    auto stA = [&](int buf) {
#pragma unroll
        for (int u = 0; u < A_LD; u++) {
            int i = tid + u * THREADS;
            int r = i / (BK / 4);
            int c4 = (i % (BK / 4)) * 4;
            As[buf][c4 + 0][r] = pa[u].x;
            As[buf][c4 + 1][r] = pa[u].y;
            As[buf][c4 + 2][r] = pa[u].z;
            As[buf][c4 + 3][r] = pa[u].w;
        }
    };
    auto stB = [&](int buf) {
#pragma unroll
        for (int u = 0; u < B_LD; u++) {
            int i = tid + u * THREADS;
            int r = i / (BN / 4);
            int c4 = (i % (BN / 4)) * 4;
            *reinterpret_cast<float4*>(&Bs[buf][r][c4]) = pb[u];
        }
    };

    float acc[TM][TN];
#pragma unroll
    for (int i = 0; i < TM; i++)
#pragma unroll
        for (int j = 0; j < TN; j++) acc[i][j] = 0.f;

    constexpr int NT = K / BK;
    ldA(0); ldB(0); stA(0); stB(0);
    __syncthreads();

#pragma unroll 1
    for (int t = 0; t < NT; t++) {
        const int buf = t & 1;
        if (t + 1 < NT) { ldA((t + 1) * BK); ldB((t + 1) * BK); }

#pragma unroll
        for (int kk = 0; kk < BK; kk++) {
            float a[TM];
            *reinterpret_cast<float4*>(&a[0]) =
                *reinterpret_cast<const float4*>(&As[buf][kk][m_idx * TM]);
            *reinterpret_cast<float4*>(&a[4]) =
                *reinterpret_cast<const float4*>(&As[buf][kk][m_idx * TM + 4]);
            float b[TN];
            *reinterpret_cast<float4*>(&b[0]) =
                *reinterpret_cast<const float4*>(&Bs[buf][kk][n_idx * 4]);
            if constexpr (TN == 8) {
                *reinterpret_cast<float4*>(&b[4]) =
                    *reinterpret_cast<const float4*>(&Bs[buf][kk][BN / 2 + n_idx * 4]);
            }
#pragma unroll
            for (int i = 0; i < TM; i++)
#pragma unroll
                for (int j = 0; j < TN; j++)
                    acc[i][j] = fmaf(a[i], b[j], acc[i][j]);
        }

        if (t + 1 < NT) { stA(buf ^ 1); stB(buf ^ 1); }
        __syncthreads();
    }

#pragma unroll
    for (int i = 0; i < TM; i++) {
        int gr = row0 + m_idx * TM + i;
        if (gr < M) {
            float4 v0 = make_float4(acc[i][0], acc[i][1], acc[i][2], acc[i][3]);
            *reinterpret_cast<float4*>(C + (size_t)gr * N + n_idx * 4) = v0;
            if constexpr (TN == 8) {
                float4 v1 = make_float4(acc[i][4], acc[i][5], acc[i][6], acc[i][7]);
                *reinterpret_cast<float4*>(C + (size_t)gr * N + BN / 2 + n_idx * 4) = v1;
            }
        }
    }
}

// ---------------------------------------------------------------------------
// SpMM: out[r,:] = sum_{e in row r} val[e] * dense[col[e],:]
// warp per row, 4-edge unroll (MLP=4 against L2 latency).
// LAYER 1: g_support -> g_h (relu); LAYER 2: g_hw -> out.
// ---------------------------------------------------------------------------
template <int LAYER>
__global__ __launch_bounds__(256)
void spmm_kernel(float* __restrict__ out_arg) {
    constexpr int D = (LAYER == 1) ? HID_DIM : OUT_DIM;
    constexpr int V = D / 32;  // 4 or 2
    const float* __restrict__ dense = (LAYER == 1) ? (const float*)g_support
                                                   : (const float*)g_hw;
    float* __restrict__ out = (LAYER == 1) ? (float*)g_h : out_arg;

    int row  = (blockIdx.x * blockDim.x + threadIdx.x) >> 5;
    int lane = threadIdx.x & 31;
    if (row >= N_NODES) return;

    int s = g_rowptr[row];
    int e = g_rowptr[row + 1];

    float acc[V];
#pragma unroll
    for (int j = 0; j < V; j++) acc[j] = 0.f;

    int i = s;
    for (; i + 3 < e; i += 4) {
        int   c0 = __ldg(&g_cols[i]),     c1 = __ldg(&g_cols[i + 1]);
        int   c2 = __ldg(&g_cols[i + 2]), c3 = __ldg(&g_cols[i + 3]);
        float v0 = __ldg(&g_vals[i]),     v1 = __ldg(&g_vals[i + 1]);
        float v2 = __ldg(&g_vals[i + 2]), v3 = __ldg(&g_vals[i + 3]);
        if constexpr (V == 4) {
            float4 d0 = __ldg(reinterpret_cast<const float4*>(dense + (size_t)c0 * D + lane * 4));
            float4 d1 = __ldg(reinterpret_cast<const float4*>(dense + (size_t)c1 * D + lane * 4));
            float4 d2 = __ldg(reinterpret_cast<const float4*>(dense + (size_t)c2 * D + lane * 4));
            float4 d3 = __ldg(reinterpret_cast<const float4*>(dense + (size_t)c3 * D + lane * 4));
            acc[0] = fmaf(v0, d0.x, acc[0]); acc[1] = fmaf(v0, d0.y, acc[1]);
            acc[2] = fmaf(v0, d0.z, acc[2]); acc[3] = fmaf(v0, d0.w, acc[3]);
            acc[0] = fmaf(v1, d1.x, acc[0]); acc[1] = fmaf(v1, d1.y, acc[1]);
            acc[2] = fmaf(v1, d1.z, acc[2]); acc[3] = fmaf(v1, d1.w, acc[3]);
            acc[0] = fmaf(v2, d2.x, acc[0]); acc[1] = fmaf(v2, d2.y, acc[1]);
            acc[2] = fmaf(v2, d2.z, acc[2]); acc[3] = fmaf(v2, d2.w, acc[3]);
            acc[0] = fmaf(v3, d3.x, acc[0]); acc[1] = fmaf(v3, d3.y, acc[1]);
            acc[2] = fmaf(v3, d3.z, acc[2]); acc[3] = fmaf(v3, d3.w, acc[3]);
        } else {
            float2 d0 = __ldg(reinterpret_cast<const float2*>(dense + (size_t)c0 * D + lane * 2));
            float2 d1 = __ldg(reinterpret_cast<const float2*>(dense + (size_t)c1 * D + lane * 2));
            float2 d2 = __ldg(reinterpret_cast<const float2*>(dense + (size_t)c2 * D + lane * 2));
            float2 d3 = __ldg(reinterpret_cast<const float2*>(dense + (size_t)c3 * D + lane * 2));
            acc[0] = fmaf(v0, d0.x, acc[0]); acc[1] = fmaf(v0, d0.y, acc[1]);
            acc[0] = fmaf(v1, d1.x, acc[0]); acc[1] = fmaf(v1, d1.y, acc[1]);
            acc[0] = fmaf(v2, d2.x, acc[0]); acc[1] = fmaf(v2, d2.y, acc[1]);
            acc[0] = fmaf(v3, d3.x, acc[0]); acc[1] = fmaf(v3, d3.y, acc[1]);
        }
    }
    for (; i < e; i++) {
        int   c0 = __ldg(&g_cols[i]);
        float v0 = __ldg(&g_vals[i]);
        if constexpr (V == 4) {
            float4 d0 = __ldg(reinterpret_cast<const float4*>(dense + (size_t)c0 * D + lane * 4));
            acc[0] = fmaf(v0, d0.x, acc[0]); acc[1] = fmaf(v0, d0.y, acc[1]);
            acc[2] = fmaf(v0, d0.z, acc[2]); acc[3] = fmaf(v0, d0.w, acc[3]);
        } else {
            float2 d0 = __ldg(reinterpret_cast<const float2*>(dense + (size_t)c0 * D + lane * 2));
            acc[0] = fmaf(v0, d0.x, acc[0]); acc[1] = fmaf(v0, d0.y, acc[1]);
        }
    }

    if constexpr (LAYER == 1) {
#pragma unroll
        for (int j = 0; j < V; j++) acc[j] = fmaxf(acc[j], 0.f);
    }

    if constexpr (V == 4) {
        float4 v = make_float4(acc[0], acc[1], acc[2], acc[3]);
        *reinterpret_cast<float4*>(out + (size_t)row * D + lane * 4) = v;
    } else {
        float2 v = make_float2(acc[0], acc[1]);
        *reinterpret_cast<float2*>(out + (size_t)row * D + lane * 2) = v;
    }
}

// ---------------------------------------------------------------------------
// Launch
// ---------------------------------------------------------------------------
extern "C" void kernel_launch(void* const* d_in, const int* in_sizes, int n_in,
                              void* d_out, int out_size) {
    const float* feature = nullptr;
    const float* W1 = nullptr;
    const float* W2 = nullptr;
    const int*   e_arr[3] = {nullptr, nullptr, nullptr};
    int e_seen = 0;

    for (int i = 0; i < n_in; i++) {
        long sz = in_sizes[i];
        if (sz == (long)N_NODES * IN_DIM)       feature = (const float*)d_in[i];
        else if (sz == (long)IN_DIM * HID_DIM)  W1 = (const float*)d_in[i];
        else if (sz == (long)HID_DIM * OUT_DIM) W2 = (const float*)d_in[i];
        else if (sz == (long)N_EDGES) { if (e_seen < 3) e_arr[e_seen++] = (const int*)d_in[i]; }
    }
    float* out = (float*)d_out;

    const int L = N_NODES + 1;
    const int SCAN_NB = (L + 2047) / 2048;  // 49

    // classify + CSR build
    zero_misc_kernel<<<(L + 255) / 256, 256>>>();
    classify_kernel<<<(CLS_SAMPLES + 255) / 256, 256>>>(e_arr[0], e_arr[1], e_arr[2]);
    select_kernel<<<1, 1>>>(e_arr[0], e_arr[1], e_arr[2]);
    hist_kernel<<<(N_EDGES / 4 + 255) / 256, 256>>>();
    scan_partial_kernel<<<SCAN_NB, 256>>>();
    scan_sums_kernel<<<1, 32>>>(SCAN_NB);
    scan_add_kernel<<<(L + 255) / 256, 256>>>();
    scatter_kernel<<<(N_EDGES / 4 + 255) / 256, 256>>>();

    // layer 1: support = X @ W1 ; h = relu(A @ support)
    gemm_kernel<1, 128, 128, 16, 8, 8, IN_DIM, HID_DIM>
        <<<(N_NODES + 127) / 128, 256>>>(feature, W1, N_NODES);
    spmm_kernel<1><<<(N_NODES * 32 + 255) / 256, 256>>>(nullptr);

    // layer 2: hw = h @ W2 ; logits = A @ hw
    gemm_kernel<2, 128, 64, 16, 8, 4, HID_DIM, OUT_DIM>
        <<<(N_NODES + 127) / 128, 256>>>(nullptr, W2, N_NODES);
    spmm_kernel<2><<<(N_NODES * 32 + 255) / 256, 256>>>(out);
}

// round 12
// speedup vs baseline: 1.0988x; 1.0988x over previous
#include <cuda_runtime.h>
#include <cuda_bf16.h>
#include <cstdint>

// Problem constants
#define N_NODES 100000
#define N_EDGES 1600000
#define IN_DIM  512
#define HID_DIM 128
#define OUT_DIM 64

// ---------------------------------------------------------------------------
// Scratch (static __device__ globals). NEVER passed as kernel arguments from
// host code (ATS shadow-address trap). All access from device code.
// ---------------------------------------------------------------------------
__device__ __align__(16) float g_support[(size_t)N_NODES * HID_DIM];
__device__ __align__(16) float g_h[(size_t)N_NODES * HID_DIM];
__device__ __align__(16) float g_hw[(size_t)N_NODES * OUT_DIM];
__device__ int   g_rowptr[N_NODES + 1];
__device__ int   g_cursor[N_NODES];
__device__ __align__(16) int   g_cols[N_EDGES];
__device__ __align__(16) float g_vals[N_EDGES];
__device__ int   g_bsums[64];
__device__ int   g_inrange[3];
__device__ const int*   g_erow_p;
__device__ const int*   g_ecol_p;
__device__ const float* g_evals_p;

// ---------------------------------------------------------------------------
// Input classification (proven in R7)
// ---------------------------------------------------------------------------
#define CLS_SAMPLES (N_EDGES / 64)   // 25000

__global__ void zero_misc_kernel() {
    int i = blockIdx.x * blockDim.x + threadIdx.x;
    if (i <= N_NODES) g_rowptr[i] = 0;
    if (i < 3) g_inrange[i] = 0;
}

__global__ void classify_kernel(const int* __restrict__ a0,
                                const int* __restrict__ a1,
                                const int* __restrict__ a2) {
    __shared__ int s[3];
    if (threadIdx.x < 3) s[threadIdx.x] = 0;
    __syncthreads();
    int i = blockIdx.x * blockDim.x + threadIdx.x;
    if (i < CLS_SAMPLES) {
        int idx = i * 64;
        if ((unsigned)__ldg(a0 + idx) < (unsigned)N_NODES) atomicAdd(&s[0], 1);
        if ((unsigned)__ldg(a1 + idx) < (unsigned)N_NODES) atomicAdd(&s[1], 1);
        if ((unsigned)__ldg(a2 + idx) < (unsigned)N_NODES) atomicAdd(&s[2], 1);
    }
    __syncthreads();
    if (threadIdx.x < 3) atomicAdd(&g_inrange[threadIdx.x], s[threadIdx.x]);
}

__global__ void select_kernel(const int* a0, const int* a1, const int* a2) {
    int c0 = g_inrange[0], c1 = g_inrange[1], c2 = g_inrange[2];
    int vi = (c0 <= c1 && c0 <= c2) ? 0 : ((c1 <= c2) ? 1 : 2);
    const int* arr[3] = {a0, a1, a2};
    int o0 = (vi == 0) ? 1 : 0;
    int o1 = (vi == 2) ? 1 : 2;
    g_erow_p  = arr[o0];                  // metadata order: row before col
    g_ecol_p  = arr[o1];
    g_evals_p = (const float*)arr[vi];
}

// ---------------------------------------------------------------------------
// CSR build — 4 edges/thread (measured win in R11: hist 14.8 -> 13.0us)
// ---------------------------------------------------------------------------
__global__ void hist_kernel() {
    const int* __restrict__ erow = g_erow_p;
    int i = (blockIdx.x * blockDim.x + threadIdx.x) * 4;
    if (i < N_EDGES) {  // N_EDGES % 4 == 0
        int4 r = *reinterpret_cast<const int4*>(erow + i);
        if ((unsigned)r.x < (unsigned)N_NODES) atomicAdd(&g_rowptr[r.x + 1], 1);
        if ((unsigned)r.y < (unsigned)N_NODES) atomicAdd(&g_rowptr[r.y + 1], 1);
        if ((unsigned)r.z < (unsigned)N_NODES) atomicAdd(&g_rowptr[r.z + 1], 1);
        if ((unsigned)r.w < (unsigned)N_NODES) atomicAdd(&g_rowptr[r.w + 1], 1);
    }
}

__global__ void scan_partial_kernel() {
    const int TPB = 256, ITEMS = 8, PER = TPB * ITEMS;
    const int L = N_NODES + 1;
    __shared__ int s[TPB];
    int base = blockIdx.x * PER + threadIdx.x * ITEMS;
    int v[ITEMS];
    int running = 0;
#pragma unroll
    for (int i = 0; i < ITEMS; i++) {
        int x = (base + i < L) ? g_rowptr[base + i] : 0;
        running += x;
        v[i] = running;
    }
    s[threadIdx.x] = running;
    __syncthreads();
    for (int off = 1; off < TPB; off <<= 1) {
        int t = (threadIdx.x >= off) ? s[threadIdx.x - off] : 0;
        __syncthreads();
        s[threadIdx.x] += t;
        __syncthreads();
    }
    int excl = s[threadIdx.x] - running;
#pragma unroll
    for (int i = 0; i < ITEMS; i++)
        if (base + i < L) g_rowptr[base + i] = v[i] + excl;
    if (threadIdx.x == TPB - 1) g_bsums[blockIdx.x] = s[TPB - 1];
}

__global__ void scan_sums_kernel(int nb) {
    if (threadIdx.x == 0 && blockIdx.x == 0) {
        int acc = 0;
        for (int i = 0; i < nb; i++) {
            int t = g_bsums[i];
            g_bsums[i] = acc;
            acc += t;
        }
    }
}

__global__ void scan_add_kernel() {
    const int L = N_NODES + 1;
    int i = blockIdx.x * blockDim.x + threadIdx.x;
    if (i < L) {
        int v = g_rowptr[i] + g_bsums[i / 2048];
        g_rowptr[i] = v;
        if (i < N_NODES) g_cursor[i] = v;
    }
}

__global__ void scatter_kernel() {
    const int*   __restrict__ erow  = g_erow_p;
    const int*   __restrict__ ecol  = g_ecol_p;
    const float* __restrict__ evals = g_evals_p;
    int i = (blockIdx.x * blockDim.x + threadIdx.x) * 4;
    if (i < N_EDGES) {
        int4   r4 = *reinterpret_cast<const int4*>(erow + i);
        int4   c4 = *reinterpret_cast<const int4*>(ecol + i);
        float4 v4 = *reinterpret_cast<const float4*>(evals + i);
        int    rr[4] = {r4.x, r4.y, r4.z, r4.w};
        int    cc[4] = {c4.x, c4.y, c4.z, c4.w};
        float  vv[4] = {v4.x, v4.y, v4.z, v4.w};
#pragma unroll
        for (int j = 0; j < 4; j++) {
            unsigned r = (unsigned)rr[j];
            if (r >= (unsigned)N_NODES) continue;
            unsigned c = (unsigned)cc[j];
            if (c >= (unsigned)N_NODES) c = N_NODES - 1;
            int p = atomicAdd(&g_cursor[r], 1);
            g_cols[p] = (int)c;
            g_vals[p] = vv[j];
        }
    }
}

// ---------------------------------------------------------------------------
// Double-buffered tiled fp32 GEMM: C[M,N] = A[M,K] @ B[K,N]
//   TM=8, TN=4 -> 32 acc regs (NO spill; R11's 64-acc version spilled under
//   launch_bounds(256,2) and regressed). One __syncthreads per K-tile.
//   GEMM1: 64x128xBK16.  GEMM2: 128x64xBK16.
// ---------------------------------------------------------------------------
template <int LAYER, int BM, int BN, int BK, int TM, int TN, int K, int N>
__global__ __launch_bounds__(256)
void gemm_kernel(const float* __restrict__ A_in, const float* __restrict__ B,
                 int M) {
    const float* __restrict__ A = (LAYER == 1) ? A_in : (const float*)g_h;
    float* __restrict__ C = (LAYER == 1) ? (float*)g_support : (float*)g_hw;

    constexpr int THREADS = 256;
    static_assert((BM / TM) * (BN / TN) == THREADS, "thread count mismatch");
    constexpr int ASTRIDE = BM + 4;
    constexpr int A_LD = BM * BK / (4 * THREADS);   // float4s per thread
    constexpr int B_LD = BK * BN / (4 * THREADS);
    static_assert(A_LD >= 1 && B_LD >= 1, "tile too small");

    __shared__ float As[2][BK][ASTRIDE];
    __shared__ float Bs[2][BK][BN];

    const int tid = threadIdx.x;
    constexpr int nGroups = BN / TN;
    const int n_idx = tid % nGroups;
    const int m_idx = tid / nGroups;
    const int row0 = blockIdx.x * BM;

    float4 pa[A_LD], pb[B_LD];

    auto ldA = [&](int k0) {
#pragma unroll
        for (int u = 0; u < A_LD; u++) {
            int i = tid + u * THREADS;
            int r = i / (BK / 4);
            int c4 = (i % (BK / 4)) * 4;
            int gr = row0 + r;
            pa[u] = (gr < M)
                ? *reinterpret_cast<const float4*>(A + (size_t)gr * K + k0 + c4)
                : make_float4(0.f, 0.f, 0.f, 0.f);
        }
    };
    auto ldB = [&](int k0) {
#pragma unroll
        for (int u = 0; u < B_LD; u++) {
            int i = tid + u * THREADS;
            int r = i / (BN / 4);
            int c4 = (i % (BN / 4)) * 4;
            pb[u] = *reinterpret_cast<const float4*>(B + (size_t)(k0 + r) * N + c4);
        }
    };
    auto stA = [&](int buf) {
#pragma unroll
        for (int u = 0; u < A_LD; u++) {
            int i = tid + u * THREADS;
            int r = i / (BK / 4);
            int c4 = (i % (BK / 4)) * 4;
            As[buf][c4 + 0][r] = pa[u].x;
            As[buf][c4 + 1][r] = pa[u].y;
            As[buf][c4 + 2][r] = pa[u].z;
            As[buf][c4 + 3][r] = pa[u].w;
        }
    };
    auto stB = [&](int buf) {
#pragma unroll
        for (int u = 0; u < B_LD; u++) {
            int i = tid + u * THREADS;
            int r = i / (BN / 4);
            int c4 = (i % (BN / 4)) * 4;
            *reinterpret_cast<float4*>(&Bs[buf][r][c4]) = pb[u];
        }
    };

    float acc[TM][TN];
#pragma unroll
    for (int i = 0; i < TM; i++)
#pragma unroll
        for (int j = 0; j < TN; j++) acc[i][j] = 0.f;

    constexpr int NT = K / BK;
    ldA(0); ldB(0); stA(0); stB(0);
    __syncthreads();

#pragma unroll 1
    for (int t = 0; t < NT; t++) {
        const int buf = t & 1;
        if (t + 1 < NT) { ldA((t + 1) * BK); ldB((t + 1) * BK); }

#pragma unroll
        for (int kk = 0; kk < BK; kk++) {
            float a[TM];
            *reinterpret_cast<float4*>(&a[0]) =
                *reinterpret_cast<const float4*>(&As[buf][kk][m_idx * TM]);
            *reinterpret_cast<float4*>(&a[4]) =
                *reinterpret_cast<const float4*>(&As[buf][kk][m_idx * TM + 4]);
            float b[TN];
            *reinterpret_cast<float4*>(&b[0]) =
                *reinterpret_cast<const float4*>(&Bs[buf][kk][n_idx * 4]);
#pragma unroll
            for (int i = 0; i < TM; i++)
#pragma unroll
                for (int j = 0; j < TN; j++)
                    acc[i][j] = fmaf(a[i], b[j], acc[i][j]);
        }

        if (t + 1 < NT) { stA(buf ^ 1); stB(buf ^ 1); }
        __syncthreads();
    }

#pragma unroll
    for (int i = 0; i < TM; i++) {
        int gr = row0 + m_idx * TM + i;
        if (gr < M) {
            float4 v0 = make_float4(acc[i][0], acc[i][1], acc[i][2], acc[i][3]);
            *reinterpret_cast<float4*>(C + (size_t)gr * N + n_idx * 4) = v0;
        }
    }
}

// ---------------------------------------------------------------------------
// SpMM: warp per row, 4-edge unroll.
// LAYER 1: g_support -> g_h (relu); LAYER 2: g_hw -> out.
// ---------------------------------------------------------------------------
template <int LAYER>
__global__ __launch_bounds__(256)
void spmm_kernel(float* __restrict__ out_arg) {
    constexpr int D = (LAYER == 1) ? HID_DIM : OUT_DIM;
    constexpr int V = D / 32;  // 4 or 2
    const float* __restrict__ dense = (LAYER == 1) ? (const float*)g_support
                                                   : (const float*)g_hw;
    float* __restrict__ out = (LAYER == 1) ? (float*)g_h : out_arg;

    int row  = (blockIdx.x * blockDim.x + threadIdx.x) >> 5;
    int lane = threadIdx.x & 31;
    if (row >= N_NODES) return;

    int s = g_rowptr[row];
    int e = g_rowptr[row + 1];

    float acc[V];
#pragma unroll
    for (int j = 0; j < V; j++) acc[j] = 0.f;

    int i = s;
    for (; i + 3 < e; i += 4) {
        int   c0 = __ldg(&g_cols[i]),     c1 = __ldg(&g_cols[i + 1]);
        int   c2 = __ldg(&g_cols[i + 2]), c3 = __ldg(&g_cols[i + 3]);
        float v0 = __ldg(&g_vals[i]),     v1 = __ldg(&g_vals[i + 1]);
        float v2 = __ldg(&g_vals[i + 2]), v3 = __ldg(&g_vals[i + 3]);
        if constexpr (V == 4) {
            float4 d0 = __ldg(reinterpret_cast<const float4*>(dense + (size_t)c0 * D + lane * 4));
            float4 d1 = __ldg(reinterpret_cast<const float4*>(dense + (size_t)c1 * D + lane * 4));
            float4 d2 = __ldg(reinterpret_cast<const float4*>(dense + (size_t)c2 * D + lane * 4));
            float4 d3 = __ldg(reinterpret_cast<const float4*>(dense + (size_t)c3 * D + lane * 4));
            acc[0] = fmaf(v0, d0.x, acc[0]); acc[1] = fmaf(v0, d0.y, acc[1]);
            acc[2] = fmaf(v0, d0.z, acc[2]); acc[3] = fmaf(v0, d0.w, acc[3]);
            acc[0] = fmaf(v1, d1.x, acc[0]); acc[1] = fmaf(v1, d1.y, acc[1]);
            acc[2] = fmaf(v1, d1.z, acc[2]); acc[3] = fmaf(v1, d1.w, acc[3]);
            acc[0] = fmaf(v2, d2.x, acc[0]); acc[1] = fmaf(v2, d2.y, acc[1]);
            acc[2] = fmaf(v2, d2.z, acc[2]); acc[3] = fmaf(v2, d2.w, acc[3]);
            acc[0] = fmaf(v3, d3.x, acc[0]); acc[1] = fmaf(v3, d3.y, acc[1]);
            acc[2] = fmaf(v3, d3.z, acc[2]); acc[3] = fmaf(v3, d3.w, acc[3]);
        } else {
            float2 d0 = __ldg(reinterpret_cast<const float2*>(dense + (size_t)c0 * D + lane * 2));
            float2 d1 = __ldg(reinterpret_cast<const float2*>(dense + (size_t)c1 * D + lane * 2));
            float2 d2 = __ldg(reinterpret_cast<const float2*>(dense + (size_t)c2 * D + lane * 2));
            float2 d3 = __ldg(reinterpret_cast<const float2*>(dense + (size_t)c3 * D + lane * 2));
            acc[0] = fmaf(v0, d0.x, acc[0]); acc[1] = fmaf(v0, d0.y, acc[1]);
            acc[0] = fmaf(v1, d1.x, acc[0]); acc[1] = fmaf(v1, d1.y, acc[1]);
            acc[0] = fmaf(v2, d2.x, acc[0]); acc[1] = fmaf(v2, d2.y, acc[1]);
            acc[0] = fmaf(v3, d3.x, acc[0]); acc[1] = fmaf(v3, d3.y, acc[1]);
        }
    }
    for (; i < e; i++) {
        int   c0 = __ldg(&g_cols[i]);
        float v0 = __ldg(&g_vals[i]);
        if constexpr (V == 4) {
            float4 d0 = __ldg(reinterpret_cast<const float4*>(dense + (size_t)c0 * D + lane * 4));
            acc[0] = fmaf(v0, d0.x, acc[0]); acc[1] = fmaf(v0, d0.y, acc[1]);
            acc[2] = fmaf(v0, d0.z, acc[2]); acc[3] = fmaf(v0, d0.w, acc[3]);
        } else {
            float2 d0 = __ldg(reinterpret_cast<const float2*>(dense + (size_t)c0 * D + lane * 2));
            acc[0] = fmaf(v0, d0.x, acc[0]); acc[1] = fmaf(v0, d0.y, acc[1]);
        }
    }

    if constexpr (LAYER == 1) {
#pragma unroll
        for (int j = 0; j < V; j++) acc[j] = fmaxf(acc[j], 0.f);
    }

    if constexpr (V == 4) {
        float4 v = make_float4(acc[0], acc[1], acc[2], acc[3]);
        *reinterpret_cast<float4*>(out + (size_t)row * D + lane * 4) = v;
    } else {
        float2 v = make_float2(acc[0], acc[1]);
        *reinterpret_cast<float2*>(out + (size_t)row * D + lane * 2) = v;
    }
}

// ---------------------------------------------------------------------------
// Launch
// ---------------------------------------------------------------------------
extern "C" void kernel_launch(void* const* d_in, const int* in_sizes, int n_in,
                              void* d_out, int out_size) {
    const float* feature = nullptr;
    const float* W1 = nullptr;
    const float* W2 = nullptr;
    const int*   e_arr[3] = {nullptr, nullptr, nullptr};
    int e_seen = 0;

    for (int i = 0; i < n_in; i++) {
        long sz = in_sizes[i];
        if (sz == (long)N_NODES * IN_DIM)       feature = (const float*)d_in[i];
        else if (sz == (long)IN_DIM * HID_DIM)  W1 = (const float*)d_in[i];
        else if (sz == (long)HID_DIM * OUT_DIM) W2 = (const float*)d_in[i];
        else if (sz == (long)N_EDGES) { if (e_seen < 3) e_arr[e_seen++] = (const int*)d_in[i]; }
    }
    float* out = (float*)d_out;

    const int L = N_NODES + 1;
    const int SCAN_NB = (L + 2047) / 2048;  // 49

    // classify + CSR build
    zero_misc_kernel<<<(L + 255) / 256, 256>>>();
    classify_kernel<<<(CLS_SAMPLES + 255) / 256, 256>>>(e_arr[0], e_arr[1], e_arr[2]);
    select_kernel<<<1, 1>>>(e_arr[0], e_arr[1], e_arr[2]);
    hist_kernel<<<(N_EDGES / 4 + 255) / 256, 256>>>();
    scan_partial_kernel<<<SCAN_NB, 256>>>();
    scan_sums_kernel<<<1, 32>>>(SCAN_NB);
    scan_add_kernel<<<(L + 255) / 256, 256>>>();
    scatter_kernel<<<(N_EDGES / 4 + 255) / 256, 256>>>();

    // layer 1: support = X @ W1 ; h = relu(A @ support)
    gemm_kernel<1, 64, 128, 16, 8, 4, IN_DIM, HID_DIM>
        <<<(N_NODES + 63) / 64, 256>>>(feature, W1, N_NODES);
    spmm_kernel<1><<<(N_NODES * 32 + 255) / 256, 256>>>(nullptr);

    // layer 2: hw = h @ W2 ; logits = A @ hw
    gemm_kernel<2, 128, 64, 16, 8, 4, HID_DIM, OUT_DIM>
        <<<(N_NODES + 127) / 128, 256>>>(nullptr, W2, N_NODES);
    spmm_kernel<2><<<(N_NODES * 32 + 255) / 256, 256>>>(out);
}

// round 14
// speedup vs baseline: 1.4345x; 1.3056x over previous
#include <cuda_runtime.h>
#include <cuda_bf16.h>
#include <cstdint>

// Problem constants
#define N_NODES 100000
#define N_EDGES 1600000
#define IN_DIM  512
#define HID_DIM 128
#define OUT_DIM 64

// ---------------------------------------------------------------------------
// Scratch (static __device__ globals). NEVER passed as kernel arguments from
// host code (ATS shadow-address trap). All access from device code.
// ---------------------------------------------------------------------------
__device__ __align__(16) float g_support[(size_t)N_NODES * HID_DIM];
__device__ __align__(16) float g_h[(size_t)N_NODES * HID_DIM];
__device__ __align__(16) float g_hw[(size_t)N_NODES * OUT_DIM];
__device__ int   g_rowptr[N_NODES + 1];
__device__ int   g_cursor[N_NODES];
__device__ __align__(16) int   g_cols[N_EDGES];
__device__ __align__(16) float g_vals[N_EDGES];
__device__ int   g_bsums[64];
__device__ const int*   g_erow_p;
__device__ const int*   g_ecol_p;
__device__ const float* g_evals_p;
// W1 transposed + split to bf16 hi/lo, layout [n][k] (N=128 rows, K=512)
__device__ __align__(16) __nv_bfloat16 g_w1h[HID_DIM * IN_DIM];
__device__ __align__(16) __nv_bfloat16 g_w1l[HID_DIM * IN_DIM];

// ---------------------------------------------------------------------------
// Combined classify+select (single CTA): vals = E-sized array whose sampled
// elements are NOT index-like; row/col kept in metadata order.
// ---------------------------------------------------------------------------
__global__ void select_combined_kernel(const int* a0, const int* a1, const int* a2) {
    __shared__ int cnt[3];
    if (threadIdx.x < 3) cnt[threadIdx.x] = 0;
    __syncthreads();
    int l0 = 0, l1 = 0, l2 = 0;
    for (int i = threadIdx.x; i < 8192; i += 256) {
        int idx = i * 195;   // max 8191*195 = 1,597,245 < N_EDGES
        if ((unsigned)__ldg(a0 + idx) < (unsigned)N_NODES) l0++;
        if ((unsigned)__ldg(a1 + idx) < (unsigned)N_NODES) l1++;
        if ((unsigned)__ldg(a2 + idx) < (unsigned)N_NODES) l2++;
    }
    atomicAdd(&cnt[0], l0);
    atomicAdd(&cnt[1], l1);
    atomicAdd(&cnt[2], l2);
    __syncthreads();
    if (threadIdx.x == 0) {
        int c0 = cnt[0], c1 = cnt[1], c2 = cnt[2];
        int vi = (c0 <= c1 && c0 <= c2) ? 0 : ((c1 <= c2) ? 1 : 2);
        const int* arr[3] = {a0, a1, a2};
        int o0 = (vi == 0) ? 1 : 0;
        int o1 = (vi == 2) ? 1 : 2;
        g_erow_p  = arr[o0];
        g_ecol_p  = arr[o1];
        g_evals_p = (const float*)arr[vi];
    }
}

// ---------------------------------------------------------------------------
// W1 transpose + bf16 hi/lo split: g_w1h/l[n*512+k] = split(W1[k*128+n])
// ---------------------------------------------------------------------------
__global__ void prep_w1_kernel(const float* __restrict__ W1) {
    int i = blockIdx.x * blockDim.x + threadIdx.x;
    if (i < IN_DIM * HID_DIM) {
        int k = i / HID_DIM, n = i % HID_DIM;
        float x = __ldg(W1 + i);
        __nv_bfloat16 hi = __float2bfloat16(x);
        __nv_bfloat16 lo = __float2bfloat16(x - __bfloat162float(hi));
        g_w1h[n * IN_DIM + k] = hi;
        g_w1l[n * IN_DIM + k] = lo;
    }
}

__global__ void zero_rowptr_kernel() {
    int i = blockIdx.x * blockDim.x + threadIdx.x;
    if (i <= N_NODES) g_rowptr[i] = 0;
}

// ---------------------------------------------------------------------------
// GEMM1 via mma.sync bf16 split-precision (3 HMMA: hh + hl + lh).
// tcgen05 is NOT available: the harness compiles via compute_103 (no 'a'),
// which rejects arch-conditional PTX. mma.sync m16n8k16 is arch-neutral.
// CTA 128x128, 512 threads, 4x4 warps, warp tile 32x32.
// K chunks of 64; register-prefetch of chunk t+1 overlaps compute of t.
// SMEM tiles row stride 36 words -> conflict-free fragment LDS.
// ---------------------------------------------------------------------------
#define G1_CH    64
#define G1_NCH   (IN_DIM / G1_CH)      // 8
#define G1_ROWW  36                    // words per tile row (32 data + 4 pad)
#define G1_AH    0
#define G1_AL    (128 * G1_ROWW)
#define G1_BH    (2 * 128 * G1_ROWW)
#define G1_BL    (3 * 128 * G1_ROWW)
#define G1_SMEMW (4 * 128 * G1_ROWW)   // 18432 words
#define G1_SMEM  (G1_SMEMW * 4)        // 73728 bytes

__device__ __forceinline__ void mma_bf16(float* c, const uint32_t* a, const uint32_t* b) {
    asm volatile(
        "mma.sync.aligned.m16n8k16.row.col.f32.bf16.bf16.f32 "
        "{%0,%1,%2,%3}, {%4,%5,%6,%7}, {%8,%9}, {%0,%1,%2,%3};"
        : "+f"(c[0]), "+f"(c[1]), "+f"(c[2]), "+f"(c[3])
        : "r"(a[0]), "r"(a[1]), "r"(a[2]), "r"(a[3]), "r"(b[0]), "r"(b[1]));
}

__global__ void __launch_bounds__(512)
gemm1_mma_kernel(const float* __restrict__ A, int M) {
    extern __shared__ uint32_t sw[];
    const int tid    = threadIdx.x;
    const int lane   = tid & 31;
    const int wid    = tid >> 5;
    const int warp_m = wid >> 2;      // 0..3
    const int warp_n = wid & 3;       // 0..3
    const int row0   = blockIdx.x * 128;
    const int lr     = lane >> 2;     // 0..7
    const int lq     = lane & 3;      // 0..3

    float4 pa[4];
    uint4  pbh[2], pbl[2];

    auto ldA = [&](int k0) {
        // 128 rows x 64 fp32 = 2048 float4; 512 thr -> 4 each
#pragma unroll
        for (int u = 0; u < 4; u++) {
            int g  = tid + u * 512;       // 0..2047
            int r  = g >> 4;              // 16 float4 per row
            int c4 = (g & 15) * 4;
            int gr = row0 + r;
            pa[u] = (gr < M)
                ? *reinterpret_cast<const float4*>(A + (size_t)gr * IN_DIM + k0 + c4)
                : make_float4(0.f, 0.f, 0.f, 0.f);
        }
    };
    auto ldB = [&](int k0) {
        // 128 n-rows x 64 bf16 = 1024 uint4 per matrix; 512 thr -> 2 each
#pragma unroll
        for (int u = 0; u < 2; u++) {
            int g = tid + u * 512;        // 0..1023
            int r = g >> 3;               // 8 uint4 per row
            int c = (g & 7) * 8;          // bf16 offset
            pbh[u] = *reinterpret_cast<const uint4*>(g_w1h + (size_t)r * IN_DIM + k0 + c);
            pbl[u] = *reinterpret_cast<const uint4*>(g_w1l + (size_t)r * IN_DIM + k0 + c);
        }
    };
    auto stAB = [&]() {
#pragma unroll
        for (int u = 0; u < 4; u++) {
            int g  = tid + u * 512;
            int r  = g >> 4;
            int cw = (g & 15) * 2;        // word offset in row (4 fp32 -> 2 words)
            float f[4] = {pa[u].x, pa[u].y, pa[u].z, pa[u].w};
            uint32_t hw[2], lw[2];
#pragma unroll
            for (int j = 0; j < 2; j++) {
                __nv_bfloat16 h0 = __float2bfloat16(f[2 * j]);
                __nv_bfloat16 h1 = __float2bfloat16(f[2 * j + 1]);
                __nv_bfloat16 l0 = __float2bfloat16(f[2 * j]     - __bfloat162float(h0));
                __nv_bfloat16 l1 = __float2bfloat16(f[2 * j + 1] - __bfloat162float(h1));
                hw[j] = (uint32_t)__bfloat16_as_ushort(h0) | ((uint32_t)__bfloat16_as_ushort(h1) << 16);
                lw[j] = (uint32_t)__bfloat16_as_ushort(l0) | ((uint32_t)__bfloat16_as_ushort(l1) << 16);
            }
            int wb = r * G1_ROWW + cw;
            sw[G1_AH + wb] = hw[0]; sw[G1_AH + wb + 1] = hw[1];
            sw[G1_AL + wb] = lw[0]; sw[G1_AL + wb + 1] = lw[1];
        }
#pragma unroll
        for (int u = 0; u < 2; u++) {
            int g  = tid + u * 512;
            int r  = g >> 3;
            int cw = (g & 7) * 4;
            int wb = r * G1_ROWW + cw;
            sw[G1_BH + wb] = pbh[u].x; sw[G1_BH + wb + 1] = pbh[u].y;
            sw[G1_BH + wb + 2] = pbh[u].z; sw[G1_BH + wb + 3] = pbh[u].w;
            sw[G1_BL + wb] = pbl[u].x; sw[G1_BL + wb + 1] = pbl[u].y;
            sw[G1_BL + wb + 2] = pbl[u].z; sw[G1_BL + wb + 3] = pbl[u].w;
        }
    };

    float acc[2][4][4];
#pragma unroll
    for (int im = 0; im < 2; im++)
#pragma unroll
        for (int in = 0; in < 4; in++)
#pragma unroll
            for (int j = 0; j < 4; j++) acc[im][in][j] = 0.f;

    ldA(0); ldB(0);

#pragma unroll 1
    for (int t = 0; t < G1_NCH; t++) {
        __syncthreads();               // prior compute done with smem
        stAB();
        __syncthreads();
        if (t + 1 < G1_NCH) { ldA((t + 1) * G1_CH); ldB((t + 1) * G1_CH); }

#pragma unroll
        for (int ks = 0; ks < G1_CH / 16; ks++) {
            const int kw = ks * 8;     // word offset of this K=16 step
            uint32_t ah[2][4], al[2][4], bh[4][2], bl[4][2];
#pragma unroll
            for (int im = 0; im < 2; im++) {
                int rb = (warp_m * 32 + im * 16 + lr) * G1_ROWW + kw + lq;
                ah[im][0] = sw[G1_AH + rb];
                ah[im][1] = sw[G1_AH + rb + 8 * G1_ROWW];
                ah[im][2] = sw[G1_AH + rb + 4];
                ah[im][3] = sw[G1_AH + rb + 8 * G1_ROWW + 4];
                al[im][0] = sw[G1_AL + rb];
                al[im][1] = sw[G1_AL + rb + 8 * G1_ROWW];
                al[im][2] = sw[G1_AL + rb + 4];
                al[im][3] = sw[G1_AL + rb + 8 * G1_ROWW + 4];
            }
#pragma unroll
            for (int in = 0; in < 4; in++) {
                int nb = (warp_n * 32 + in * 8 + lr) * G1_ROWW + kw + lq;
                bh[in][0] = sw[G1_BH + nb];
                bh[in][1] = sw[G1_BH + nb + 4];
                bl[in][0] = sw[G1_BL + nb];
                bl[in][1] = sw[G1_BL + nb + 4];
            }
#pragma unroll
            for (int im = 0; im < 2; im++)
#pragma unroll
                for (int in = 0; in < 4; in++) {
                    mma_bf16(acc[im][in], ah[im], bh[in]);
                    mma_bf16(acc[im][in], ah[im], bl[in]);
                    mma_bf16(acc[im][in], al[im], bh[in]);
                }
        }
    }

    // epilogue: c0/c1 -> (row, n..n+1); c2/c3 -> (row+8, n..n+1)
#pragma unroll
    for (int im = 0; im < 2; im++) {
        int m0 = row0 + warp_m * 32 + im * 16 + lr;
#pragma unroll
        for (int in = 0; in < 4; in++) {
            int n = warp_n * 32 + in * 8 + lq * 2;
            if (m0 < M)
                *reinterpret_cast<float2*>(&g_support[(size_t)m0 * HID_DIM + n]) =
                    make_float2(acc[im][in][0], acc[im][in][1]);
            if (m0 + 8 < M)
                *reinterpret_cast<float2*>(&g_support[(size_t)(m0 + 8) * HID_DIM + n]) =
                    make_float2(acc[im][in][2], acc[im][in][3]);
        }
    }
}

// ---------------------------------------------------------------------------
// CSR build — 4 edges/thread
// ---------------------------------------------------------------------------
__global__ void hist_kernel() {
    const int* __restrict__ erow = g_erow_p;
    int i = (blockIdx.x * blockDim.x + threadIdx.x) * 4;
    if (i < N_EDGES) {
        int4 r = *reinterpret_cast<const int4*>(erow + i);
        if ((unsigned)r.x < (unsigned)N_NODES) atomicAdd(&g_rowptr[r.x + 1], 1);
        if ((unsigned)r.y < (unsigned)N_NODES) atomicAdd(&g_rowptr[r.y + 1], 1);
        if ((unsigned)r.z < (unsigned)N_NODES) atomicAdd(&g_rowptr[r.z + 1], 1);
        if ((unsigned)r.w < (unsigned)N_NODES) atomicAdd(&g_rowptr[r.w + 1], 1);
    }
}

__global__ void scan_partial_kernel() {
    const int TPB = 256, ITEMS = 8, PER = TPB * ITEMS;
    const int L = N_NODES + 1;
    __shared__ int s[TPB];
    int base = blockIdx.x * PER + threadIdx.x * ITEMS;
    int v[ITEMS];
    int running = 0;
#pragma unroll
    for (int i = 0; i < ITEMS; i++) {
        int x = (base + i < L) ? g_rowptr[base + i] : 0;
        running += x;
        v[i] = running;
    }
    s[threadIdx.x] = running;
    __syncthreads();
    for (int off = 1; off < TPB; off <<= 1) {
        int t = (threadIdx.x >= off) ? s[threadIdx.x - off] : 0;
        __syncthreads();
        s[threadIdx.x] += t;
        __syncthreads();
    }
    int excl = s[threadIdx.x] - running;
#pragma unroll
    for (int i = 0; i < ITEMS; i++)
        if (base + i < L) g_rowptr[base + i] = v[i] + excl;
    if (threadIdx.x == TPB - 1) g_bsums[blockIdx.x] = s[TPB - 1];
}

__global__ void scan_sums_kernel(int nb) {
    if (threadIdx.x == 0 && blockIdx.x == 0) {
        int acc = 0;
        for (int i = 0; i < nb; i++) {
            int t = g_bsums[i];
            g_bsums[i] = acc;
            acc += t;
        }
    }
}

__global__ void scan_add_kernel() {
    const int L = N_NODES + 1;
    int i = blockIdx.x * blockDim.x + threadIdx.x;
    if (i < L) {
        int v = g_rowptr[i] + g_bsums[i / 2048];
        g_rowptr[i] = v;
        if (i < N_NODES) g_cursor[i] = v;
    }
}

__global__ void scatter_kernel() {
    const int*   __restrict__ erow  = g_erow_p;
    const int*   __restrict__ ecol  = g_ecol_p;
    const float* __restrict__ evals = g_evals_p;
    int i = (blockIdx.x * blockDim.x + threadIdx.x) * 4;
    if (i < N_EDGES) {
        int4   r4 = *reinterpret_cast<const int4*>(erow + i);
        int4   c4 = *reinterpret_cast<const int4*>(ecol + i);
        float4 v4 = *reinterpret_cast<const float4*>(evals + i);
        int    rr[4] = {r4.x, r4.y, r4.z, r4.w};
        int    cc[4] = {c4.x, c4.y, c4.z, c4.w};
        float  vv[4] = {v4.x, v4.y, v4.z, v4.w};
#pragma unroll
        for (int j = 0; j < 4; j++) {
            unsigned r = (unsigned)rr[j];
            if (r >= (unsigned)N_NODES) continue;
            unsigned c = (unsigned)cc[j];
            if (c >= (unsigned)N_NODES) c = N_NODES - 1;
            int p = atomicAdd(&g_cursor[r], 1);
            g_cols[p] = (int)c;
            g_vals[p] = vv[j];
        }
    }
}

// ---------------------------------------------------------------------------
// fp32 double-buffered GEMM (R12, proven) — layer 2 only.
// ---------------------------------------------------------------------------
template <int LAYER, int BM, int BN, int BK, int TM, int TN, int K, int N>
__global__ __launch_bounds__(256)
void gemm_kernel(const float* __restrict__ A_in, const float* __restrict__ B,
                 int M) {
    const float* __restrict__ A = (LAYER == 1) ? A_in : (const float*)g_h;
    float* __restrict__ C = (LAYER == 1) ? (float*)g_support : (float*)g_hw;

    constexpr int THREADS = 256;
    static_assert((BM / TM) * (BN / TN) == THREADS, "thread count mismatch");
    constexpr int ASTRIDE = BM + 4;
    constexpr int A_LD = BM * BK / (4 * THREADS);
    constexpr int B_LD = BK * BN / (4 * THREADS);

    __shared__ float As[2][BK][ASTRIDE];
    __shared__ float Bs[2][BK][BN];

    const int tid = threadIdx.x;
    constexpr int nGroups = BN / TN;
    const int n_idx = tid % nGroups;
    const int m_idx = tid / nGroups;
    const int row0 = blockIdx.x * BM;

    float4 pa[A_LD], pb[B_LD];

    auto ldA = [&](int k0) {
#pragma unroll
        for (int u = 0; u < A_LD; u++) {
            int i = tid + u * THREADS;
            int r = i / (BK / 4);
            int c4 = (i % (BK / 4)) * 4;
            int gr = row0 + r;
            pa[u] = (gr < M)
                ? *reinterpret_cast<const float4*>(A + (size_t)gr * K + k0 + c4)
                : make_float4(0.f, 0.f, 0.f, 0.f);
        }
    };
    auto ldB = [&](int k0) {
#pragma unroll
        for (int u = 0; u < B_LD; u++) {
            int i = tid + u * THREADS;
            int r = i / (BN / 4);
            int c4 = (i % (BN / 4)) * 4;
            pb[u] = *reinterpret_cast<const float4*>(B + (size_t)(k0 + r) * N + c4);
        }
    };
    auto stA = [&](int buf) {
#pragma unroll
        for (int u = 0; u < A_LD; u++) {
            int i = tid + u * THREADS;
            int r = i / (BK / 4);
            int c4 = (i % (BK / 4)) * 4;
            As[buf][c4 + 0][r] = pa[u].x;
            As[buf][c4 + 1][r] = pa[u].y;
            As[buf][c4 + 2][r] = pa[u].z;
            As[buf][c4 + 3][r] = pa[u].w;
        }
    };
    auto stB = [&](int buf) {
#pragma unroll
        for (int u = 0; u < B_LD; u++) {
            int i = tid + u * THREADS;
            int r = i / (BN / 4);
            int c4 = (i % (BN / 4)) * 4;
            *reinterpret_cast<float4*>(&Bs[buf][r][c4]) = pb[u];
        }
    };

    float acc[TM][TN];
#pragma unroll
    for (int i = 0; i < TM; i++)
#pragma unroll
        for (int j = 0; j < TN; j++) acc[i][j] = 0.f;

    constexpr int NT = K / BK;
    ldA(0); ldB(0); stA(0); stB(0);
    __syncthreads();

#pragma unroll 1
    for (int t = 0; t < NT; t++) {
        const int buf = t & 1;
        if (t + 1 < NT) { ldA((t + 1) * BK); ldB((t + 1) * BK); }

#pragma unroll
        for (int kk = 0; kk < BK; kk++) {
            float a[TM];
            *reinterpret_cast<float4*>(&a[0]) =
                *reinterpret_cast<const float4*>(&As[buf][kk][m_idx * TM]);
            *reinterpret_cast<float4*>(&a[4]) =
                *reinterpret_cast<const float4*>(&As[buf][kk][m_idx * TM + 4]);
            float b[TN];
            *reinterpret_cast<float4*>(&b[0]) =
                *reinterpret_cast<const float4*>(&Bs[buf][kk][n_idx * 4]);
#pragma unroll
            for (int i = 0; i < TM; i++)
#pragma unroll
                for (int j = 0; j < TN; j++)
                    acc[i][j] = fmaf(a[i], b[j], acc[i][j]);
        }

        if (t + 1 < NT) { stA(buf ^ 1); stB(buf ^ 1); }
        __syncthreads();
    }

#pragma unroll
    for (int i = 0; i < TM; i++) {
        int gr = row0 + m_idx * TM + i;
        if (gr < M) {
            float4 v0 = make_float4(acc[i][0], acc[i][1], acc[i][2], acc[i][3]);
            *reinterpret_cast<float4*>(C + (size_t)gr * N + n_idx * 4) = v0;
        }
    }
}

// ---------------------------------------------------------------------------
// SpMM: warp per row, 4-edge unroll (R12, proven).
// ---------------------------------------------------------------------------
template <int LAYER>
__global__ __launch_bounds__(256)
void spmm_kernel(float* __restrict__ out_arg) {
    constexpr int D = (LAYER == 1) ? HID_DIM : OUT_DIM;
    constexpr int V = D / 32;  // 4 or 2
    const float* __restrict__ dense = (LAYER == 1) ? (const float*)g_support
                                                   : (const float*)g_hw;
    float* __restrict__ out = (LAYER == 1) ? (float*)g_h : out_arg;

    int row  = (blockIdx.x * blockDim.x + threadIdx.x) >> 5;
    int lane = threadIdx.x & 31;
    if (row >= N_NODES) return;

    int s = g_rowptr[row];
    int e = g_rowptr[row + 1];

    float acc[V];
#pragma unroll
    for (int j = 0; j < V; j++) acc[j] = 0.f;

    int i = s;
    for (; i + 3 < e; i += 4) {
        int   c0 = __ldg(&g_cols[i]),     c1 = __ldg(&g_cols[i + 1]);
        int   c2 = __ldg(&g_cols[i + 2]), c3 = __ldg(&g_cols[i + 3]);
        float v0 = __ldg(&g_vals[i]),     v1 = __ldg(&g_vals[i + 1]);
        float v2 = __ldg(&g_vals[i + 2]), v3 = __ldg(&g_vals[i + 3]);
        if constexpr (V == 4) {
            float4 d0 = __ldg(reinterpret_cast<const float4*>(dense + (size_t)c0 * D + lane * 4));
            float4 d1 = __ldg(reinterpret_cast<const float4*>(dense + (size_t)c1 * D + lane * 4));
            float4 d2 = __ldg(reinterpret_cast<const float4*>(dense + (size_t)c2 * D + lane * 4));
            float4 d3 = __ldg(reinterpret_cast<const float4*>(dense + (size_t)c3 * D + lane * 4));
            acc[0] = fmaf(v0, d0.x, acc[0]); acc[1] = fmaf(v0, d0.y, acc[1]);
            acc[2] = fmaf(v0, d0.z, acc[2]); acc[3] = fmaf(v0, d0.w, acc[3]);
            acc[0] = fmaf(v1, d1.x, acc[0]); acc[1] = fmaf(v1, d1.y, acc[1]);
            acc[2] = fmaf(v1, d1.z, acc[2]); acc[3] = fmaf(v1, d1.w, acc[3]);
            acc[0] = fmaf(v2, d2.x, acc[0]); acc[1] = fmaf(v2, d2.y, acc[1]);
            acc[2] = fmaf(v2, d2.z, acc[2]); acc[3] = fmaf(v2, d2.w, acc[3]);
            acc[0] = fmaf(v3, d3.x, acc[0]); acc[1] = fmaf(v3, d3.y, acc[1]);
            acc[2] = fmaf(v3, d3.z, acc[2]); acc[3] = fmaf(v3, d3.w, acc[3]);
        } else {
            float2 d0 = __ldg(reinterpret_cast<const float2*>(dense + (size_t)c0 * D + lane * 2));
            float2 d1 = __ldg(reinterpret_cast<const float2*>(dense + (size_t)c1 * D + lane * 2));
            float2 d2 = __ldg(reinterpret_cast<const float2*>(dense + (size_t)c2 * D + lane * 2));
            float2 d3 = __ldg(reinterpret_cast<const float2*>(dense + (size_t)c3 * D + lane * 2));
            acc[0] = fmaf(v0, d0.x, acc[0]); acc[1] = fmaf(v0, d0.y, acc[1]);
            acc[0] = fmaf(v1, d1.x, acc[0]); acc[1] = fmaf(v1, d1.y, acc[1]);
            acc[0] = fmaf(v2, d2.x, acc[0]); acc[1] = fmaf(v2, d2.y, acc[1]);
            acc[0] = fmaf(v3, d3.x, acc[0]); acc[1] = fmaf(v3, d3.y, acc[1]);
        }
    }
    for (; i < e; i++) {
        int   c0 = __ldg(&g_cols[i]);
        float v0 = __ldg(&g_vals[i]);
        if constexpr (V == 4) {
            float4 d0 = __ldg(reinterpret_cast<const float4*>(dense + (size_t)c0 * D + lane * 4));
            acc[0] = fmaf(v0, d0.x, acc[0]); acc[1] = fmaf(v0, d0.y, acc[1]);
            acc[2] = fmaf(v0, d0.z, acc[2]); acc[3] = fmaf(v0, d0.w, acc[3]);
        } else {
            float2 d0 = __ldg(reinterpret_cast<const float2*>(dense + (size_t)c0 * D + lane * 2));
            acc[0] = fmaf(v0, d0.x, acc[0]); acc[1] = fmaf(v0, d0.y, acc[1]);
        }
    }

    if constexpr (LAYER == 1) {
#pragma unroll
        for (int j = 0; j < V; j++) acc[j] = fmaxf(acc[j], 0.f);
    }

    if constexpr (V == 4) {
        float4 v = make_float4(acc[0], acc[1], acc[2], acc[3]);
        *reinterpret_cast<float4*>(out + (size_t)row * D + lane * 4) = v;
    } else {
        float2 v = make_float2(acc[0], acc[1]);
        *reinterpret_cast<float2*>(out + (size_t)row * D + lane * 2) = v;
    }
}

// ---------------------------------------------------------------------------
// Launch. gemm1 placed 4th (the launch ncu empirically captures).
// ---------------------------------------------------------------------------
extern "C" void kernel_launch(void* const* d_in, const int* in_sizes, int n_in,
                              void* d_out, int out_size) {
    const float* feature = nullptr;
    const float* W1 = nullptr;
    const float* W2 = nullptr;
    const int*   e_arr[3] = {nullptr, nullptr, nullptr};
    int e_seen = 0;

    for (int i = 0; i < n_in; i++) {
        long sz = in_sizes[i];
        if (sz == (long)N_NODES * IN_DIM)       feature = (const float*)d_in[i];
        else if (sz == (long)IN_DIM * HID_DIM)  W1 = (const float*)d_in[i];
        else if (sz == (long)HID_DIM * OUT_DIM) W2 = (const float*)d_in[i];
        else if (sz == (long)N_EDGES) { if (e_seen < 3) e_arr[e_seen++] = (const int*)d_in[i]; }
    }
    float* out = (float*)d_out;

    const int L = N_NODES + 1;
    const int SCAN_NB = (L + 2047) / 2048;  // 49

    cudaFuncSetAttribute(gemm1_mma_kernel,
                         cudaFuncAttributeMaxDynamicSharedMemorySize, G1_SMEM);

    select_combined_kernel<<<1, 256>>>(e_arr[0], e_arr[1], e_arr[2]);
    prep_w1_kernel<<<(IN_DIM * HID_DIM + 255) / 256, 256>>>(W1);
    zero_rowptr_kernel<<<(L + 255) / 256, 256>>>();

    // layer 1 GEMM: support = X @ W1 (bf16-split mma.sync)
    gemm1_mma_kernel<<<(N_NODES + 127) / 128, 512, G1_SMEM>>>(feature, N_NODES);

    // CSR build
    hist_kernel<<<(N_EDGES / 4 + 255) / 256, 256>>>();
    scan_partial_kernel<<<SCAN_NB, 256>>>();
    scan_sums_kernel<<<1, 32>>>(SCAN_NB);
    scan_add_kernel<<<(L + 255) / 256, 256>>>();
    scatter_kernel<<<(N_EDGES / 4 + 255) / 256, 256>>>();

    // h = relu(A @ support)
    spmm_kernel<1><<<(N_NODES * 32 + 255) / 256, 256>>>(nullptr);

    // layer 2: hw = h @ W2 (fp32) ; logits = A @ hw
    gemm_kernel<2, 128, 64, 16, 8, 4, HID_DIM, OUT_DIM>
        <<<(N_NODES + 127) / 128, 256>>>(nullptr, W2, N_NODES);
    spmm_kernel<2><<<(N_NODES * 32 + 255) / 256, 256>>>(out);
}

// round 16
// speedup vs baseline: 1.4457x; 1.0078x over previous
#include <cuda_runtime.h>
#include <cuda_bf16.h>
#include <cstdint>

// Problem constants
#define N_NODES 100000
#define N_EDGES 1600000
#define IN_DIM  512
#define HID_DIM 128
#define OUT_DIM 64

// ---------------------------------------------------------------------------
// Scratch (static __device__ globals). NEVER passed as kernel arguments from
// host code (ATS shadow-address trap). All access from device code.
// ---------------------------------------------------------------------------
__device__ __align__(16) float g_support[(size_t)N_NODES * HID_DIM];
__device__ __align__(16) float g_h[(size_t)N_NODES * HID_DIM];
__device__ __align__(16) float g_hw[(size_t)N_NODES * OUT_DIM];
__device__ int   g_rowptr[N_NODES + 1];
__device__ int   g_cursor[N_NODES];
__device__ __align__(16) int   g_cols[N_EDGES];
__device__ __align__(16) float g_vals[N_EDGES];
__device__ int   g_bsums[64];
__device__ const int*   g_erow_p;
__device__ const int*   g_ecol_p;
__device__ const float* g_evals_p;
// W1 transposed + split to bf16 hi/lo, layout [n][k] (N=128 rows, K=512)
__device__ __align__(16) __nv_bfloat16 g_w1h[HID_DIM * IN_DIM];
__device__ __align__(16) __nv_bfloat16 g_w1l[HID_DIM * IN_DIM];

// ---------------------------------------------------------------------------
// Combined classify+select (single CTA): vals = E-sized array whose sampled
// elements are NOT index-like; row/col kept in metadata order.
// ---------------------------------------------------------------------------
__global__ void select_combined_kernel(const int* a0, const int* a1, const int* a2) {
    __shared__ int cnt[3];
    if (threadIdx.x < 3) cnt[threadIdx.x] = 0;
    __syncthreads();
    int l0 = 0, l1 = 0, l2 = 0;
    for (int i = threadIdx.x; i < 8192; i += 256) {
        int idx = i * 195;   // max 8191*195 = 1,597,245 < N_EDGES
        if ((unsigned)__ldg(a0 + idx) < (unsigned)N_NODES) l0++;
        if ((unsigned)__ldg(a1 + idx) < (unsigned)N_NODES) l1++;
        if ((unsigned)__ldg(a2 + idx) < (unsigned)N_NODES) l2++;
    }
    atomicAdd(&cnt[0], l0);
    atomicAdd(&cnt[1], l1);
    atomicAdd(&cnt[2], l2);
    __syncthreads();
    if (threadIdx.x == 0) {
        int c0 = cnt[0], c1 = cnt[1], c2 = cnt[2];
        int vi = (c0 <= c1 && c0 <= c2) ? 0 : ((c1 <= c2) ? 1 : 2);
        const int* arr[3] = {a0, a1, a2};
        int o0 = (vi == 0) ? 1 : 0;
        int o1 = (vi == 2) ? 1 : 2;
        g_erow_p  = arr[o0];
        g_ecol_p  = arr[o1];
        g_evals_p = (const float*)arr[vi];
    }
}

// ---------------------------------------------------------------------------
// W1 transpose + bf16 hi/lo split: g_w1h/l[n*512+k] = split(W1[k*128+n])
// ---------------------------------------------------------------------------
__global__ void prep_w1_kernel(const float* __restrict__ W1) {
    int i = blockIdx.x * blockDim.x + threadIdx.x;
    if (i < IN_DIM * HID_DIM) {
        int k = i / HID_DIM, n = i % HID_DIM;
        float x = __ldg(W1 + i);
        __nv_bfloat16 hi = __float2bfloat16(x);
        __nv_bfloat16 lo = __float2bfloat16(x - __bfloat162float(hi));
        g_w1h[n * IN_DIM + k] = hi;
        g_w1l[n * IN_DIM + k] = lo;
    }
}

__global__ void zero_rowptr_kernel() {
    int i = blockIdx.x * blockDim.x + threadIdx.x;
    if (i <= N_NODES) g_rowptr[i] = 0;
}

// ---------------------------------------------------------------------------
// GEMM1 via mma.sync bf16 split-precision (3 HMMA: hh + hl + lh).
// tcgen05 is NOT available: the harness compiles via compute_103 (no 'a'),
// which rejects arch-conditional PTX. mma.sync m16n8k16 is arch-neutral.
// CTA 128x128, 512 threads, 4x4 warps, warp tile 32x32.
// K chunks of 64; register-prefetch of chunk t+1 overlaps compute of t.
// SMEM tiles row stride 36 words -> conflict-free fragment LDS.
// ---------------------------------------------------------------------------
#define G1_CH    64
#define G1_NCH   (IN_DIM / G1_CH)      // 8
#define G1_ROWW  36                    // words per tile row (32 data + 4 pad)
#define G1_AH    0
#define G1_AL    (128 * G1_ROWW)
#define G1_BH    (2 * 128 * G1_ROWW)
#define G1_BL    (3 * 128 * G1_ROWW)
#define G1_SMEMW (4 * 128 * G1_ROWW)   // 18432 words
#define G1_SMEM  (G1_SMEMW * 4)        // 73728 bytes

__device__ __forceinline__ void mma_bf16(float* c, const uint32_t* a, const uint32_t* b) {
    asm volatile(
        "mma.sync.aligned.m16n8k16.row.col.f32.bf16.bf16.f32 "
        "{%0,%1,%2,%3}, {%4,%5,%6,%7}, {%8,%9}, {%0,%1,%2,%3};"
        : "+f"(c[0]), "+f"(c[1]), "+f"(c[2]), "+f"(c[3])
        : "r"(a[0]), "r"(a[1]), "r"(a[2]), "r"(a[3]), "r"(b[0]), "r"(b[1]));
}

__global__ void __launch_bounds__(512)
gemm1_mma_kernel(const float* __restrict__ A, int M) {
    extern __shared__ uint32_t sw[];
    const int tid    = threadIdx.x;
    const int lane   = tid & 31;
    const int wid    = tid >> 5;
    const int warp_m = wid >> 2;      // 0..3
    const int warp_n = wid & 3;       // 0..3
    const int row0   = blockIdx.x * 128;
    const int lr     = lane >> 2;     // 0..7
    const int lq     = lane & 3;      // 0..3

    float4 pa[4];
    uint4  pbh[2], pbl[2];

    auto ldA = [&](int k0) {
        // 128 rows x 64 fp32 = 2048 float4; 512 thr -> 4 each
#pragma unroll
        for (int u = 0; u < 4; u++) {
            int g  = tid + u * 512;       // 0..2047
            int r  = g >> 4;              // 16 float4 per row
            int c4 = (g & 15) * 4;
            int gr = row0 + r;
            pa[u] = (gr < M)
                ? *reinterpret_cast<const float4*>(A + (size_t)gr * IN_DIM + k0 + c4)
                : make_float4(0.f, 0.f, 0.f, 0.f);
        }
    };
    auto ldB = [&](int k0) {
        // 128 n-rows x 64 bf16 = 1024 uint4 per matrix; 512 thr -> 2 each
#pragma unroll
        for (int u = 0; u < 2; u++) {
            int g = tid + u * 512;        // 0..1023
            int r = g >> 3;               // 8 uint4 per row
            int c = (g & 7) * 8;          // bf16 offset
            pbh[u] = *reinterpret_cast<const uint4*>(g_w1h + (size_t)r * IN_DIM + k0 + c);
            pbl[u] = *reinterpret_cast<const uint4*>(g_w1l + (size_t)r * IN_DIM + k0 + c);
        }
    };
    auto stAB = [&]() {
#pragma unroll
        for (int u = 0; u < 4; u++) {
            int g  = tid + u * 512;
            int r  = g >> 4;
            int cw = (g & 15) * 2;        // word offset in row (4 fp32 -> 2 words)
            float f[4] = {pa[u].x, pa[u].y, pa[u].z, pa[u].w};
            uint32_t hw[2], lw[2];
#pragma unroll
            for (int j = 0; j < 2; j++) {
                __nv_bfloat16 h0 = __float2bfloat16(f[2 * j]);
                __nv_bfloat16 h1 = __float2bfloat16(f[2 * j + 1]);
                __nv_bfloat16 l0 = __float2bfloat16(f[2 * j]     - __bfloat162float(h0));
                __nv_bfloat16 l1 = __float2bfloat16(f[2 * j + 1] - __bfloat162float(h1));
                hw[j] = (uint32_t)__bfloat16_as_ushort(h0) | ((uint32_t)__bfloat16_as_ushort(h1) << 16);
                lw[j] = (uint32_t)__bfloat16_as_ushort(l0) | ((uint32_t)__bfloat16_as_ushort(l1) << 16);
            }
            int wb = r * G1_ROWW + cw;
            sw[G1_AH + wb] = hw[0]; sw[G1_AH + wb + 1] = hw[1];
            sw[G1_AL + wb] = lw[0]; sw[G1_AL + wb + 1] = lw[1];
        }
#pragma unroll
        for (int u = 0; u < 2; u++) {
            int g  = tid + u * 512;
            int r  = g >> 3;
            int cw = (g & 7) * 4;
            int wb = r * G1_ROWW + cw;
            sw[G1_BH + wb] = pbh[u].x; sw[G1_BH + wb + 1] = pbh[u].y;
            sw[G1_BH + wb + 2] = pbh[u].z; sw[G1_BH + wb + 3] = pbh[u].w;
            sw[G1_BL + wb] = pbl[u].x; sw[G1_BL + wb + 1] = pbl[u].y;
            sw[G1_BL + wb + 2] = pbl[u].z; sw[G1_BL + wb + 3] = pbl[u].w;
        }
    };

    float acc[2][4][4];
#pragma unroll
    for (int im = 0; im < 2; im++)
#pragma unroll
        for (int in = 0; in < 4; in++)
#pragma unroll
            for (int j = 0; j < 4; j++) acc[im][in][j] = 0.f;

    ldA(0); ldB(0);

#pragma unroll 1
    for (int t = 0; t < G1_NCH; t++) {
        __syncthreads();               // prior compute done with smem
        stAB();
        __syncthreads();
        if (t + 1 < G1_NCH) { ldA((t + 1) * G1_CH); ldB((t + 1) * G1_CH); }

#pragma unroll
        for (int ks = 0; ks < G1_CH / 16; ks++) {
            const int kw = ks * 8;     // word offset of this K=16 step
            uint32_t ah[2][4], al[2][4], bh[4][2], bl[4][2];
#pragma unroll
            for (int im = 0; im < 2; im++) {
                int rb = (warp_m * 32 + im * 16 + lr) * G1_ROWW + kw + lq;
                ah[im][0] = sw[G1_AH + rb];
                ah[im][1] = sw[G1_AH + rb + 8 * G1_ROWW];
                ah[im][2] = sw[G1_AH + rb + 4];
                ah[im][3] = sw[G1_AH + rb + 8 * G1_ROWW + 4];
                al[im][0] = sw[G1_AL + rb];
                al[im][1] = sw[G1_AL + rb + 8 * G1_ROWW];
                al[im][2] = sw[G1_AL + rb + 4];
                al[im][3] = sw[G1_AL + rb + 8 * G1_ROWW + 4];
            }
#pragma unroll
            for (int in = 0; in < 4; in++) {
                int nb = (warp_n * 32 + in * 8 + lr) * G1_ROWW + kw + lq;
                bh[in][0] = sw[G1_BH + nb];
                bh[in][1] = sw[G1_BH + nb + 4];
                bl[in][0] = sw[G1_BL + nb];
                bl[in][1] = sw[G1_BL + nb + 4];
            }
#pragma unroll
            for (int im = 0; im < 2; im++)
#pragma unroll
                for (int in = 0; in < 4; in++) {
                    mma_bf16(acc[im][in], ah[im], bh[in]);
                    mma_bf16(acc[im][in], ah[im], bl[in]);
                    mma_bf16(acc[im][in], al[im], bh[in]);
                }
        }
    }

    // epilogue: c0/c1 -> (row, n..n+1); c2/c3 -> (row+8, n..n+1)
#pragma unroll
    for (int im = 0; im < 2; im++) {
        int m0 = row0 + warp_m * 32 + im * 16 + lr;
#pragma unroll
        for (int in = 0; in < 4; in++) {
            int n = warp_n * 32 + in * 8 + lq * 2;
            if (m0 < M)
                *reinterpret_cast<float2*>(&g_support[(size_t)m0 * HID_DIM + n]) =
                    make_float2(acc[im][in][0], acc[im][in][1]);
            if (m0 + 8 < M)
                *reinterpret_cast<float2*>(&g_support[(size_t)(m0 + 8) * HID_DIM + n]) =
                    make_float2(acc[im][in][2], acc[im][in][3]);
        }
    }
}

// ---------------------------------------------------------------------------
// CSR build — 4 edges/thread
// ---------------------------------------------------------------------------
__global__ void hist_kernel() {
    const int* __restrict__ erow = g_erow_p;
    int i = (blockIdx.x * blockDim.x + threadIdx.x) * 4;
    if (i < N_EDGES) {
        int4 r = *reinterpret_cast<const int4*>(erow + i);
        if ((unsigned)r.x < (unsigned)N_NODES) atomicAdd(&g_rowptr[r.x + 1], 1);
        if ((unsigned)r.y < (unsigned)N_NODES) atomicAdd(&g_rowptr[r.y + 1], 1);
        if ((unsigned)r.z < (unsigned)N_NODES) atomicAdd(&g_rowptr[r.z + 1], 1);
        if ((unsigned)r.w < (unsigned)N_NODES) atomicAdd(&g_rowptr[r.w + 1], 1);
    }
}

__global__ void scan_partial_kernel() {
    const int TPB = 256, ITEMS = 8, PER = TPB * ITEMS;
    const int L = N_NODES + 1;
    __shared__ int s[TPB];
    int base = blockIdx.x * PER + threadIdx.x * ITEMS;
    int v[ITEMS];
    int running = 0;
#pragma unroll
    for (int i = 0; i < ITEMS; i++) {
        int x = (base + i < L) ? g_rowptr[base + i] : 0;
        running += x;
        v[i] = running;
    }
    s[threadIdx.x] = running;
    __syncthreads();
    for (int off = 1; off < TPB; off <<= 1) {
        int t = (threadIdx.x >= off) ? s[threadIdx.x - off] : 0;
        __syncthreads();
        s[threadIdx.x] += t;
        __syncthreads();
    }
    int excl = s[threadIdx.x] - running;
#pragma unroll
    for (int i = 0; i < ITEMS; i++)
        if (base + i < L) g_rowptr[base + i] = v[i] + excl;
    if (threadIdx.x == TPB - 1) g_bsums[blockIdx.x] = s[TPB - 1];
}

__global__ void scan_sums_kernel(int nb) {
    if (threadIdx.x == 0 && blockIdx.x == 0) {
        int acc = 0;
        for (int i = 0; i < nb; i++) {
            int t = g_bsums[i];
            g_bsums[i] = acc;
            acc += t;
        }
    }
}

__global__ void scan_add_kernel() {
    const int L = N_NODES + 1;
    int i = blockIdx.x * blockDim.x + threadIdx.x;
    if (i < L) {
        int v = g_rowptr[i] + g_bsums[i / 2048];
        g_rowptr[i] = v;
        if (i < N_NODES) g_cursor[i] = v;
    }
}

__global__ void scatter_kernel() {
    const int*   __restrict__ erow  = g_erow_p;
    const int*   __restrict__ ecol  = g_ecol_p;
    const float* __restrict__ evals = g_evals_p;
    int i = (blockIdx.x * blockDim.x + threadIdx.x) * 4;
    if (i < N_EDGES) {
        int4   r4 = *reinterpret_cast<const int4*>(erow + i);
        int4   c4 = *reinterpret_cast<const int4*>(ecol + i);
        float4 v4 = *reinterpret_cast<const float4*>(evals + i);
        int    rr[4] = {r4.x, r4.y, r4.z, r4.w};
        int    cc[4] = {c4.x, c4.y, c4.z, c4.w};
        float  vv[4] = {v4.x, v4.y, v4.z, v4.w};
#pragma unroll
        for (int j = 0; j < 4; j++) {
            unsigned r = (unsigned)rr[j];
            if (r >= (unsigned)N_NODES) continue;
            unsigned c = (unsigned)cc[j];
            if (c >= (unsigned)N_NODES) c = N_NODES - 1;
            int p = atomicAdd(&g_cursor[r], 1);
            g_cols[p] = (int)c;
            g_vals[p] = vv[j];
        }
    }
}

// ---------------------------------------------------------------------------
// fp32 double-buffered GEMM (R12, proven) — layer 2 only.
// ---------------------------------------------------------------------------
template <int LAYER, int BM, int BN, int BK, int TM, int TN, int K, int N>
__global__ __launch_bounds__(256)
void gemm_kernel(const float* __restrict__ A_in, const float* __restrict__ B,
                 int M) {
    const float* __restrict__ A = (LAYER == 1) ? A_in : (const float*)g_h;
    float* __restrict__ C = (LAYER == 1) ? (float*)g_support : (float*)g_hw;

    constexpr int THREADS = 256;
    static_assert((BM / TM) * (BN / TN) == THREADS, "thread count mismatch");
    constexpr int ASTRIDE = BM + 4;
    constexpr int A_LD = BM * BK / (4 * THREADS);
    constexpr int B_LD = BK * BN / (4 * THREADS);

    __shared__ float As[2][BK][ASTRIDE];
    __shared__ float Bs[2][BK][BN];

    const int tid = threadIdx.x;
    constexpr int nGroups = BN / TN;
    const int n_idx = tid % nGroups;
    const int m_idx = tid / nGroups;
    const int row0 = blockIdx.x * BM;

    float4 pa[A_LD], pb[B_LD];

    auto ldA = [&](int k0) {
#pragma unroll
        for (int u = 0; u < A_LD; u++) {
            int i = tid + u * THREADS;
            int r = i / (BK / 4);
            int c4 = (i % (BK / 4)) * 4;
            int gr = row0 + r;
            pa[u] = (gr < M)
                ? *reinterpret_cast<const float4*>(A + (size_t)gr * K + k0 + c4)
                : make_float4(0.f, 0.f, 0.f, 0.f);
        }
    };
    auto ldB = [&](int k0) {
#pragma unroll
        for (int u = 0; u < B_LD; u++) {
            int i = tid + u * THREADS;
            int r = i / (BN / 4);
            int c4 = (i % (BN / 4)) * 4;
            pb[u] = *reinterpret_cast<const float4*>(B + (size_t)(k0 + r) * N + c4);
        }
    };
    auto stA = [&](int buf) {
#pragma unroll
        for (int u = 0; u < A_LD; u++) {
            int i = tid + u * THREADS;
            int r = i / (BK / 4);
            int c4 = (i % (BK / 4)) * 4;
            As[buf][c4 + 0][r] = pa[u].x;
            As[buf][c4 + 1][r] = pa[u].y;
            As[buf][c4 + 2][r] = pa[u].z;
            As[buf][c4 + 3][r] = pa[u].w;
        }
    };
    auto stB = [&](int buf) {
#pragma unroll
        for (int u = 0; u < B_LD; u++) {
            int i = tid + u * THREADS;
            int r = i / (BN / 4);
            int c4 = (i % (BN / 4)) * 4;
            *reinterpret_cast<float4*>(&Bs[buf][r][c4]) = pb[u];
        }
    };

    float acc[TM][TN];
#pragma unroll
    for (int i = 0; i < TM; i++)
#pragma unroll
        for (int j = 0; j < TN; j++) acc[i][j] = 0.f;

    constexpr int NT = K / BK;
    ldA(0); ldB(0); stA(0); stB(0);
    __syncthreads();

#pragma unroll 1
    for (int t = 0; t < NT; t++) {
        const int buf = t & 1;
        if (t + 1 < NT) { ldA((t + 1) * BK); ldB((t + 1) * BK); }

#pragma unroll
        for (int kk = 0; kk < BK; kk++) {
            float a[TM];
            *reinterpret_cast<float4*>(&a[0]) =
                *reinterpret_cast<const float4*>(&As[buf][kk][m_idx * TM]);
            *reinterpret_cast<float4*>(&a[4]) =
                *reinterpret_cast<const float4*>(&As[buf][kk][m_idx * TM + 4]);
            float b[TN];
            *reinterpret_cast<float4*>(&b[0]) =
                *reinterpret_cast<const float4*>(&Bs[buf][kk][n_idx * 4]);
#pragma unroll
            for (int i = 0; i < TM; i++)
#pragma unroll
                for (int j = 0; j < TN; j++)
                    acc[i][j] = fmaf(a[i], b[j], acc[i][j]);
        }

        if (t + 1 < NT) { stA(buf ^ 1); stB(buf ^ 1); }
        __syncthreads();
    }

#pragma unroll
    for (int i = 0; i < TM; i++) {
        int gr = row0 + m_idx * TM + i;
        if (gr < M) {
            float4 v0 = make_float4(acc[i][0], acc[i][1], acc[i][2], acc[i][3]);
            *reinterpret_cast<float4*>(C + (size_t)gr * N + n_idx * 4) = v0;
        }
    }
}

// ---------------------------------------------------------------------------
// SpMM: warp per row, 4-edge unroll (R12, proven).
// ---------------------------------------------------------------------------
template <int LAYER>
__global__ __launch_bounds__(256)
void spmm_kernel(float* __restrict__ out_arg) {
    constexpr int D = (LAYER == 1) ? HID_DIM : OUT_DIM;
    constexpr int V = D / 32;  // 4 or 2
    const float* __restrict__ dense = (LAYER == 1) ? (const float*)g_support
                                                   : (const float*)g_hw;
    float* __restrict__ out = (LAYER == 1) ? (float*)g_h : out_arg;

    int row  = (blockIdx.x * blockDim.x + threadIdx.x) >> 5;
    int lane = threadIdx.x & 31;
    if (row >= N_NODES) return;

    int s = g_rowptr[row];
    int e = g_rowptr[row + 1];

    float acc[V];
#pragma unroll
    for (int j = 0; j < V; j++) acc[j] = 0.f;

    int i = s;
    for (; i + 3 < e; i += 4) {
        int   c0 = __ldg(&g_cols[i]),     c1 = __ldg(&g_cols[i + 1]);
        int   c2 = __ldg(&g_cols[i + 2]), c3 = __ldg(&g_cols[i + 3]);
        float v0 = __ldg(&g_vals[i]),     v1 = __ldg(&g_vals[i + 1]);
        float v2 = __ldg(&g_vals[i + 2]), v3 = __ldg(&g_vals[i + 3]);
        if constexpr (V == 4) {
            float4 d0 = __ldg(reinterpret_cast<const float4*>(dense + (size_t)c0 * D + lane * 4));
            float4 d1 = __ldg(reinterpret_cast<const float4*>(dense + (size_t)c1 * D + lane * 4));
            float4 d2 = __ldg(reinterpret_cast<const float4*>(dense + (size_t)c2 * D + lane * 4));
            float4 d3 = __ldg(reinterpret_cast<const float4*>(dense + (size_t)c3 * D + lane * 4));
            acc[0] = fmaf(v0, d0.x, acc[0]); acc[1] = fmaf(v0, d0.y, acc[1]);
            acc[2] = fmaf(v0, d0.z, acc[2]); acc[3] = fmaf(v0, d0.w, acc[3]);
            acc[0] = fmaf(v1, d1.x, acc[0]); acc[1] = fmaf(v1, d1.y, acc[1]);
            acc[2] = fmaf(v1, d1.z, acc[2]); acc[3] = fmaf(v1, d1.w, acc[3]);
            acc[0] = fmaf(v2, d2.x, acc[0]); acc[1] = fmaf(v2, d2.y, acc[1]);
            acc[2] = fmaf(v2, d2.z, acc[2]); acc[3] = fmaf(v2, d2.w, acc[3]);
            acc[0] = fmaf(v3, d3.x, acc[0]); acc[1] = fmaf(v3, d3.y, acc[1]);
            acc[2] = fmaf(v3, d3.z, acc[2]); acc[3] = fmaf(v3, d3.w, acc[3]);
        } else {
            float2 d0 = __ldg(reinterpret_cast<const float2*>(dense + (size_t)c0 * D + lane * 2));
            float2 d1 = __ldg(reinterpret_cast<const float2*>(dense + (size_t)c1 * D + lane * 2));
            float2 d2 = __ldg(reinterpret_cast<const float2*>(dense + (size_t)c2 * D + lane * 2));
            float2 d3 = __ldg(reinterpret_cast<const float2*>(dense + (size_t)c3 * D + lane * 2));
            acc[0] = fmaf(v0, d0.x, acc[0]); acc[1] = fmaf(v0, d0.y, acc[1]);
            acc[0] = fmaf(v1, d1.x, acc[0]); acc[1] = fmaf(v1, d1.y, acc[1]);
            acc[0] = fmaf(v2, d2.x, acc[0]); acc[1] = fmaf(v2, d2.y, acc[1]);
            acc[0] = fmaf(v3, d3.x, acc[0]); acc[1] = fmaf(v3, d3.y, acc[1]);
        }
    }
    for (; i < e; i++) {
        int   c0 = __ldg(&g_cols[i]);
        float v0 = __ldg(&g_vals[i]);
        if constexpr (V == 4) {
            float4 d0 = __ldg(reinterpret_cast<const float4*>(dense + (size_t)c0 * D + lane * 4));
            acc[0] = fmaf(v0, d0.x, acc[0]); acc[1] = fmaf(v0, d0.y, acc[1]);
            acc[2] = fmaf(v0, d0.z, acc[2]); acc[3] = fmaf(v0, d0.w, acc[3]);
        } else {
            float2 d0 = __ldg(reinterpret_cast<const float2*>(dense + (size_t)c0 * D + lane * 2));
            acc[0] = fmaf(v0, d0.x, acc[0]); acc[1] = fmaf(v0, d0.y, acc[1]);
        }
    }

    if constexpr (LAYER == 1) {
#pragma unroll
        for (int j = 0; j < V; j++) acc[j] = fmaxf(acc[j], 0.f);
    }

    if constexpr (V == 4) {
        float4 v = make_float4(acc[0], acc[1], acc[2], acc[3]);
        *reinterpret_cast<float4*>(out + (size_t)row * D + lane * 4) = v;
    } else {
        float2 v = make_float2(acc[0], acc[1]);
        *reinterpret_cast<float2*>(out + (size_t)row * D + lane * 2) = v;
    }
}

// ---------------------------------------------------------------------------
// Launch. gemm1 placed 4th (the launch ncu empirically captures).
// ---------------------------------------------------------------------------
extern "C" void kernel_launch(void* const* d_in, const int* in_sizes, int n_in,
                              void* d_out, int out_size) {
    const float* feature = nullptr;
    const float* W1 = nullptr;
    const float* W2 = nullptr;
    const int*   e_arr[3] = {nullptr, nullptr, nullptr};
    int e_seen = 0;

    for (int i = 0; i < n_in; i++) {
        long sz = in_sizes[i];
        if (sz == (long)N_NODES * IN_DIM)       feature = (const float*)d_in[i];
        else if (sz == (long)IN_DIM * HID_DIM)  W1 = (const float*)d_in[i];
        else if (sz == (long)HID_DIM * OUT_DIM) W2 = (const float*)d_in[i];
        else if (sz == (long)N_EDGES) { if (e_seen < 3) e_arr[e_seen++] = (const int*)d_in[i]; }
    }
    float* out = (float*)d_out;

    const int L = N_NODES + 1;
    const int SCAN_NB = (L + 2047) / 2048;  // 49

    cudaFuncSetAttribute(gemm1_mma_kernel,
                         cudaFuncAttributeMaxDynamicSharedMemorySize, G1_SMEM);

    select_combined_kernel<<<1, 256>>>(e_arr[0], e_arr[1], e_arr[2]);
    prep_w1_kernel<<<(IN_DIM * HID_DIM + 255) / 256, 256>>>(W1);
    zero_rowptr_kernel<<<(L + 255) / 256, 256>>>();

    // layer 1 GEMM: support = X @ W1 (bf16-split mma.sync)
    gemm1_mma_kernel<<<(N_NODES + 127) / 128, 512, G1_SMEM>>>(feature, N_NODES);

    // CSR build
    hist_kernel<<<(N_EDGES / 4 + 255) / 256, 256>>>();
    scan_partial_kernel<<<SCAN_NB, 256>>>();
    scan_sums_kernel<<<1, 32>>>(SCAN_NB);
    scan_add_kernel<<<(L + 255) / 256, 256>>>();
    scatter_kernel<<<(N_EDGES / 4 + 255) / 256, 256>>>();

    // h = relu(A @ support)
    spmm_kernel<1><<<(N_NODES * 32 + 255) / 256, 256>>>(nullptr);

    // layer 2: hw = h @ W2 (fp32) ; logits = A @ hw
    gemm_kernel<2, 128, 64, 16, 8, 4, HID_DIM, OUT_DIM>
        <<<(N_NODES + 127) / 128, 256>>>(nullptr, W2, N_NODES);
    spmm_kernel<2><<<(N_NODES * 32 + 255) / 256, 256>>>(out);
}